// round 14
// baseline (speedup 1.0000x reference)
#include <cuda_runtime.h>
#include <cuda_bf16.h>
#include <math.h>
#include <stdint.h>

// ---------------- problem constants ----------------
#define NB      16
#define BT      128            // NB * 8
#define HWN     196
#define ROWS    25088          // BT * HWN
#define CC      768
#define NHEAD   12
#define HD      64
#define TOKENS  3136

// ---------------- scratch (device globals; no allocs allowed) ----------------
__device__ __align__(16) __nv_bfloat16 g_xab [25088u*768u];
__device__ __align__(16) __nv_bfloat16 g_xdb [25088u*768u];
__device__ __align__(16) __nv_bfloat16 g_xdnb[25088u*768u];
__device__ __align__(16) __nv_bfloat16 g_qb  [25088u*768u];
__device__ __align__(16) __nv_bfloat16 g_qab [25088u*768u];   // stage-a Q (overlap)
__device__ __align__(16) __nv_bfloat16 g_kvb [25088u*1536u];
__device__ __align__(16) __nv_bfloat16 g_ob  [25088u*768u];
__device__ float g_xd [25088u*768u];               // fp32 x_d (Xsub)
__device__ __align__(16) uint32_t g_wp[2359296u];  // packed bf16x2 k-pair weights

__device__ __forceinline__ float gelu_f(float x) {
    return 0.5f * x * (1.0f + erff(x * 0.70710678118654752f));
}
__device__ __forceinline__ uint32_t pack_bf(float x, float y) {
    __nv_bfloat162 v = __float22bfloat162_rn(make_float2(x, y));
    return *reinterpret_cast<uint32_t*>(&v);
}
__device__ __forceinline__ void mma_bf16(float* c, const uint32_t* a,
                                         uint32_t b0, uint32_t b1) {
    asm volatile(
        "mma.sync.aligned.m16n8k16.row.col.f32.bf16.bf16.f32 "
        "{%0,%1,%2,%3}, {%4,%5,%6,%7}, {%8,%9}, {%0,%1,%2,%3};\n"
        : "+f"(c[0]), "+f"(c[1]), "+f"(c[2]), "+f"(c[3])
        : "r"(a[0]), "r"(a[1]), "r"(a[2]), "r"(a[3]), "r"(b0), "r"(b1));
}
__device__ __forceinline__ void cp16(uint32_t saddr, const void* g) {
    asm volatile("cp.async.ca.shared.global [%0], [%1], 16;\n"
                 :: "r"(saddr), "l"(g));
}
__device__ __forceinline__ void ldsm_x4(uint32_t& r0, uint32_t& r1,
                                        uint32_t& r2, uint32_t& r3, uint32_t addr) {
    asm volatile("ldmatrix.sync.aligned.m8n8.x4.shared.b16 {%0,%1,%2,%3}, [%4];"
                 : "=r"(r0), "=r"(r1), "=r"(r2), "=r"(r3) : "r"(addr));
}

// ------- weight pack: W[768][N] f32 -> Wp[384][N] u32 (k-pairs) -------------
// z=0,2 (Wq) scaled by 0.125 (exact pow2 -> bit-identical bf16 rounding).
__global__ void packw6_kernel(const float* __restrict__ W0, const float* __restrict__ W1,
                              const float* __restrict__ W2, const float* __restrict__ W3,
                              const float* __restrict__ W4, const float* __restrict__ W5,
                              uint32_t* __restrict__ wp)
{
    const int z = blockIdx.z;
    const float* W; uint32_t off; int N; float sc;
    switch (z) {
        case 0: W = W0; off = 0u;       N = 768;  sc = 0.125f; break;
        case 1: W = W1; off = 294912u;  N = 1536; sc = 1.f;    break;
        case 2: W = W2; off = 884736u;  N = 768;  sc = 0.125f; break;
        case 3: W = W3; off = 1179648u; N = 1536; sc = 1.f;    break;
        case 4: W = W4; off = 1769472u; N = 768;  sc = 1.f;    break;
        default:W = W5; off = 2064384u; N = 768;  sc = 1.f;    break;
    }
    int n  = blockIdx.x * 256 + threadIdx.x;
    int kp = blockIdx.y * 8;
    if (n >= N) return;
    uint32_t* Wp = wp + off;
    #pragma unroll
    for (int i = 0; i < 8; i++) {
        float a = W[(size_t)(2*(kp+i)  ) * N + n] * sc;
        float b = W[(size_t)(2*(kp+i)+1) * N + n] * sc;
        Wp[(size_t)(kp+i) * N + n] = pack_bf(a, b);
    }
}

// ---------------- gather: x_in -> xa_b, xd_b, xd_f32, pool base + zero ------
__global__ void gather_kernel(const float* __restrict__ x_in,
                              __nv_bfloat16* __restrict__ xab,
                              __nv_bfloat16* __restrict__ xdb,
                              float* __restrict__ xd,
                              float* __restrict__ out)
{
    int row = blockIdx.x;              // bt*196 + s
    int bt  = row / HWN, s = row % HWN;
    int b   = bt >> 3,  t2 = bt & 7;
    int tt  = t2 * 2;
    int nt_a = tt >> 2,     t_a = tt & 3;
    int nt_d = (tt+1) >> 2, t_d = (tt+1) & 3;
    size_t base_a = ((size_t)b*TOKENS + (size_t)nt_a*784 + s*4 + t_a) * CC;
    size_t base_d = ((size_t)b*TOKENS + (size_t)nt_d*784 + s*4 + t_d) * CC;

    if (threadIdx.x == 224) out[ROWS + row] = 0.f;   // x_d_out accumulator init

    float suma = 0.f, sumd = 0.f;
    int c4 = threadIdx.x * 4;
    if (c4 < CC) {
        float4 va = *(const float4*)&x_in[base_a + c4];
        float4 vd = *(const float4*)&x_in[base_d + c4];
        uint2 pa; pa.x = pack_bf(va.x, va.y); pa.y = pack_bf(va.z, va.w);
        uint2 pd; pd.x = pack_bf(vd.x, vd.y); pd.y = pack_bf(vd.z, vd.w);
        *(uint2*)&xab[(size_t)row*CC + c4] = pa;
        *(uint2*)&xdb[(size_t)row*CC + c4] = pd;
        *(float4*)&xd[(size_t)row*CC + c4] = vd;
        suma = va.x+va.y+va.z+va.w;
        sumd = vd.x+vd.y+vd.z+vd.w;
    }
    __shared__ float ra[256], rd[256];
    ra[threadIdx.x] = suma; rd[threadIdx.x] = sumd;
    __syncthreads();
    for (int st = 128; st > 0; st >>= 1) {
        if (threadIdx.x < st) {
            ra[threadIdx.x] += ra[threadIdx.x + st];
            rd[threadIdx.x] += rd[threadIdx.x + st];
        }
        __syncthreads();
    }
    if (threadIdx.x == 0)
        out[row] = 0.5f * (rd[0] - ra[0]) * (1.f/768.f);
}

// ---------------- bf16 GEMM (R10 config: scalar LDS, CTA 256x128) -----------
// At the legacy mma.sync HMMA pipe ceiling (~2048 cyc/SMSP per k-tile) —
// do not touch the mainloop.
#define APITCH 20
#define BPITCH 136
#define A_STG  (256*APITCH)
#define B_STG  (16*BPITCH)
#define STG_U32 (A_STG + B_STG)
#define GEMM_SMEM (4 * STG_U32 * 4)

#define EPI_BIAS     0
#define EPI_GELU     1
#define EPI_GELU_SUB 2

__global__ __launch_bounds__(256, 1) void gemm_bf(
    const __nv_bfloat16* __restrict__ A, const uint32_t* __restrict__ Wp,
    const float* __restrict__ bias, float bsc,
    __nv_bfloat16* __restrict__ Yb,
    const float* __restrict__ Xsub,
    float* __restrict__ msum, float sgn,
    int M, int N, int K, int epi)
{
    extern __shared__ uint32_t smg[];
    const uint32_t sbase = (uint32_t)__cvta_generic_to_shared(smg);

    const int tid  = threadIdx.x;
    const int bm   = blockIdx.y * 256;
    const int bn   = blockIdx.x * 128;
    const int lane = tid & 31, warp = tid >> 5;
    const int wm   = (warp >> 1) * 64;
    const int wn   = (warp & 1) * 64;
    const int gg   = lane >> 2;
    const int qp   = lane & 3;

    const int nk = K / 32;

    float acc[4][8][4];
    #pragma unroll
    for (int i=0;i<4;i++)
        #pragma unroll
        for (int j=0;j<8;j++)
            #pragma unroll
            for (int r=0;r<4;r++) acc[i][j][r]=0.f;

    auto issue = [&](int kt) {
        const int stg = kt & 3;
        const uint32_t sa = sbase + (stg * STG_U32) * 4;
        #pragma unroll
        for (int i = 0; i < 4; i++) {
            int c = tid + i*256;
            int row = c >> 2, kb = c & 3;
            cp16(sa + (row * APITCH + kb * 4) * 4,
                 &A[(size_t)(bm + row) * K + kt*32 + kb*8]);
        }
        const uint32_t sb = sa + A_STG * 4;
        #pragma unroll
        for (int i = 0; i < 2; i++) {
            int c = tid + i*256;
            int kp = c >> 5, n4 = (c & 31) * 4;
            cp16(sb + (kp * BPITCH + n4) * 4,
                 &Wp[(size_t)(kt*16 + kp) * N + bn + n4]);
        }
        asm volatile("cp.async.commit_group;\n" ::: "memory");
    };

    issue(0); issue(1); issue(2);

    for (int kt = 0; kt < nk; kt++) {
        if (kt < nk - 2)       asm volatile("cp.async.wait_group 2;\n" ::: "memory");
        else if (kt == nk - 2) asm volatile("cp.async.wait_group 1;\n" ::: "memory");
        else                   asm volatile("cp.async.wait_group 0;\n" ::: "memory");
        __syncthreads();
        if (kt + 3 < nk) issue(kt + 3);

        const uint32_t* As_ = smg + (kt & 3) * STG_U32;
        const uint32_t* Bs_ = As_ + A_STG;

        #pragma unroll
        for (int kk = 0; kk < 2; kk++) {
            uint32_t af[4][4], bf[8][2];
            #pragma unroll
            for (int mi = 0; mi < 4; mi++) {
                int rb = wm + mi*16;
                af[mi][0] = As_[(rb+gg  )*APITCH + kk*8 + qp    ];
                af[mi][1] = As_[(rb+gg+8)*APITCH + kk*8 + qp    ];
                af[mi][2] = As_[(rb+gg  )*APITCH + kk*8 + qp + 4];
                af[mi][3] = As_[(rb+gg+8)*APITCH + kk*8 + qp + 4];
            }
            #pragma unroll
            for (int ni = 0; ni < 8; ni++) {
                int cb = wn + ni*8;
                bf[ni][0] = Bs_[(kk*8 + qp    )*BPITCH + cb + gg];
                bf[ni][1] = Bs_[(kk*8 + qp + 4)*BPITCH + cb + gg];
            }
            #pragma unroll
            for (int mi = 0; mi < 4; mi++)
                #pragma unroll
                for (int ni = 0; ni < 8; ni++)
                    mma_bf16(acc[mi][ni], af[mi], bf[ni][0], bf[ni][1]);
        }
    }

    // ---- epilogue ----
    if (epi == EPI_BIAS) {
        #pragma unroll
        for (int mi=0; mi<4; mi++) {
            const int r0 = bm + wm + mi*16 + gg;
            const int r1 = r0 + 8;
            #pragma unroll
            for (int ni=0; ni<8; ni++) {
                const int c = bn + wn + ni*8 + qp*2;
                const float b0v = __ldg(&bias[c])   * bsc;
                const float b1v = __ldg(&bias[c+1]) * bsc;
                *(uint32_t*)&Yb[(size_t)r0*N + c] =
                    pack_bf(acc[mi][ni][0] + b0v, acc[mi][ni][1] + b1v);
                *(uint32_t*)&Yb[(size_t)r1*N + c] =
                    pack_bf(acc[mi][ni][2] + b0v, acc[mi][ni][3] + b1v);
            }
        }
    } else {
        float rs[4][2];
        #pragma unroll
        for (int mi=0;mi<4;mi++) { rs[mi][0]=0.f; rs[mi][1]=0.f; }
        #pragma unroll
        for (int mi=0; mi<4; mi++) {
            const int r0 = bm + wm + mi*16 + gg;
            const int r1 = r0 + 8;
            #pragma unroll
            for (int ni=0; ni<8; ni++) {
                const int c = bn + wn + ni*8 + qp*2;
                const float b0v = __ldg(&bias[c]);
                const float b1v = __ldg(&bias[c+1]);
                float v00 = acc[mi][ni][0] + b0v, v01 = acc[mi][ni][1] + b1v;
                float v10 = acc[mi][ni][2] + b0v, v11 = acc[mi][ni][3] + b1v;
                if (epi == EPI_GELU) {
                    rs[mi][0] += gelu_f(v00) + gelu_f(v01);
                    rs[mi][1] += gelu_f(v10) + gelu_f(v11);
                } else {  // GELU_SUB
                    float2 x0 = *(const float2*)&Xsub[(size_t)r0*N + c];
                    float2 x1 = *(const float2*)&Xsub[(size_t)r1*N + c];
                    float o00 = x0.x - gelu_f(v00), o01 = x0.y - gelu_f(v01);
                    float o10 = x1.x - gelu_f(v10), o11 = x1.y - gelu_f(v11);
                    rs[mi][0] += o00 + o01;
                    rs[mi][1] += o10 + o11;
                    *(uint32_t*)&Yb[(size_t)r0*N + c] = pack_bf(o00, o01);
                    *(uint32_t*)&Yb[(size_t)r1*N + c] = pack_bf(o10, o11);
                }
            }
        }
        #pragma unroll
        for (int mi=0; mi<4; mi++)
            #pragma unroll
            for (int hf=0; hf<2; hf++) {
                float s = rs[mi][hf];
                s += __shfl_xor_sync(0xffffffffu, s, 1);
                s += __shfl_xor_sync(0xffffffffu, s, 2);
                if (qp == 0) {
                    int row = bm + wm + mi*16 + gg + hf*8;
                    atomicAdd(&msum[row], s * sgn * (1.f/768.f));
                }
            }
    }
}

// ---------------- bf16 tensor-core attention, per (bt, head) ----------------
// Q pre-scaled by 1/8 (folded into Wq). 12 unmasked tiles + 1 masked tile.
#define AT_WARPS   7
#define AT_THREADS 224
#define NKP 208
#define KSP2 36
#define VTP2 116
#define ATTN_SMEM ((NKP*KSP2 + 64*VTP2) * 4)

__global__ __launch_bounds__(AT_THREADS, 2) void attn_tc(
    const __nv_bfloat16* __restrict__ Qb, const __nv_bfloat16* __restrict__ KVb,
    __nv_bfloat16* __restrict__ Ob)
{
    extern __shared__ uint32_t smu[];
    uint32_t* Ks = smu;                    // [208][36]
    uint32_t* Vt = smu + NKP*KSP2;         // [64][116]
    unsigned short* Vs16 = reinterpret_cast<unsigned short*>(Vt);
    const uint32_t KsAddr = (uint32_t)__cvta_generic_to_shared(Ks);
    const uint32_t VtAddr = (uint32_t)__cvta_generic_to_shared(Vt);

    const int bt = blockIdx.x / NHEAD;
    const int h  = blockIdx.x % NHEAD;
    const int tid  = threadIdx.x;
    const int w    = tid >> 5;
    const int lane = tid & 31;
    const int g    = lane >> 2;
    const int qp   = lane & 3;

    // ---- Q fragments first (global LDG; overlaps with smem staging) ----
    uint32_t qa[2][4][4];
    #pragma unroll
    for (int mi = 0; mi < 2; mi++) {
        int r0 = 32*w + 16*mi + g, r1 = r0 + 8;
        const uint32_t* q0 = reinterpret_cast<const uint32_t*>(Qb)
                           + ((size_t)bt*HWN + r0)*384 + h*32;
        const uint32_t* q1 = reinterpret_cast<const uint32_t*>(Qb)
                           + ((size_t)bt*HWN + r1)*384 + h*32;
        bool v0 = (r0 < HWN), v1 = (r1 < HWN);
        #pragma unroll
        for (int kk = 0; kk < 4; kk++) {
            qa[mi][kk][0] = v0 ? q0[8*kk + qp    ] : 0u;
            qa[mi][kk][1] = v1 ? q1[8*kk + qp    ] : 0u;
            qa[mi][kk][2] = v0 ? q0[8*kk + qp + 4] : 0u;
            qa[mi][kk][3] = v1 ? q1[8*kk + qp + 4] : 0u;
        }
    }

    // ---- stage K (u32 copy) and V^T (bf16 scatter) ----
    const uint32_t* kvu = reinterpret_cast<const uint32_t*>(KVb)
                        + (size_t)bt * HWN * 768 + h * 32;
    for (int idx = tid; idx < HWN * 32; idx += AT_THREADS) {
        int r = idx >> 5, j = idx & 31;
        Ks[r*KSP2 + j] = kvu[(size_t)r*768 + j];
        uint32_t v = kvu[(size_t)r*768 + 384 + j];
        int d0 = 2*j;
        Vs16[(d0  )*(VTP2*2) + r] = (unsigned short)(v & 0xffffu);
        Vs16[(d0+1)*(VTP2*2) + r] = (unsigned short)(v >> 16);
    }
    for (int idx = tid; idx < 12*KSP2; idx += AT_THREADS)
        Ks[(196 + idx/KSP2)*KSP2 + idx%KSP2] = 0u;
    for (int idx = tid; idx < 64*6; idx += AT_THREADS)
        Vt[(idx/6)*VTP2 + 98 + idx%6] = 0u;
    __syncthreads();

    const int rowo = (lane & 7) + ((lane >> 4) & 1) * 8;
    const int ko4  = ((lane >> 3) & 1) * 4;
    const uint32_t aK = KsAddr + (rowo * KSP2 + ko4) * 4;
    const uint32_t aV = VtAddr + (rowo * VTP2 + ko4) * 4;

    float oacc[2][8][4];
    #pragma unroll
    for (int mi=0; mi<2; mi++)
        #pragma unroll
        for (int di=0; di<8; di++)
            #pragma unroll
            for (int r=0; r<4; r++) oacc[mi][di][r] = 0.f;
    float lp[2][2] = {{0.f,0.f},{0.f,0.f}};

    for (int nt = 0; nt < 13; nt++) {
        const int j0 = nt * 16;
        float c[2][2][4];
        #pragma unroll
        for (int mi=0;mi<2;mi++)
            #pragma unroll
            for (int hf=0;hf<2;hf++)
                #pragma unroll
                for (int r=0;r<4;r++) c[mi][hf][r]=0.f;

        #pragma unroll
        for (int kk = 0; kk < 4; kk++) {
            uint32_t kb0h0, kb1h0, kb0h1, kb1h1;
            ldsm_x4(kb0h0, kb1h0, kb0h1, kb1h1,
                    aK + (j0 * KSP2 + 8*kk) * 4);
            mma_bf16(c[0][0], qa[0][kk], kb0h0, kb1h0);
            mma_bf16(c[1][0], qa[1][kk], kb0h0, kb1h0);
            mma_bf16(c[0][1], qa[0][kk], kb0h1, kb1h1);
            mma_bf16(c[1][1], qa[1][kk], kb0h1, kb1h1);
        }

        // exp; scale already folded into Q. C-frag becomes PV A-frag.
        uint32_t pa[2][4];
        if (nt < 12) {
            #pragma unroll
            for (int mi = 0; mi < 2; mi++) {
                #pragma unroll
                for (int hf = 0; hf < 2; hf++) {
                    float p00 = __expf(fminf(c[mi][hf][0], 80.f));
                    float p01 = __expf(fminf(c[mi][hf][1], 80.f));
                    float p10 = __expf(fminf(c[mi][hf][2], 80.f));
                    float p11 = __expf(fminf(c[mi][hf][3], 80.f));
                    lp[mi][0] += p00 + p01;
                    lp[mi][1] += p10 + p11;
                    pa[mi][2*hf    ] = pack_bf(p00, p01);
                    pa[mi][2*hf + 1] = pack_bf(p10, p11);
                }
            }
        } else {
            #pragma unroll
            for (int mi = 0; mi < 2; mi++) {
                #pragma unroll
                for (int hf = 0; hf < 2; hf++) {
                    const int col0 = j0 + 8*hf + 2*qp;
                    const bool m0 = (col0     < HWN);
                    const bool m1 = (col0 + 1 < HWN);
                    float p00 = m0 ? __expf(fminf(c[mi][hf][0], 80.f)) : 0.f;
                    float p01 = m1 ? __expf(fminf(c[mi][hf][1], 80.f)) : 0.f;
                    float p10 = m0 ? __expf(fminf(c[mi][hf][2], 80.f)) : 0.f;
                    float p11 = m1 ? __expf(fminf(c[mi][hf][3], 80.f)) : 0.f;
                    lp[mi][0] += p00 + p01;
                    lp[mi][1] += p10 + p11;
                    pa[mi][2*hf    ] = pack_bf(p00, p01);
                    pa[mi][2*hf + 1] = pack_bf(p10, p11);
                }
            }
        }

        const int jp = nt * 8;
        #pragma unroll
        for (int di = 0; di < 8; di += 2) {
            uint32_t vb0a, vb1a, vb0b, vb1b;
            ldsm_x4(vb0a, vb1a, vb0b, vb1b,
                    aV + (8*di * VTP2 + jp) * 4);
            mma_bf16(oacc[0][di  ], pa[0], vb0a, vb1a);
            mma_bf16(oacc[1][di  ], pa[1], vb0a, vb1a);
            mma_bf16(oacc[0][di+1], pa[0], vb0b, vb1b);
            mma_bf16(oacc[1][di+1], pa[1], vb0b, vb1b);
        }
    }

    float inv[2][2];
    #pragma unroll
    for (int mi = 0; mi < 2; mi++)
        #pragma unroll
        for (int hf = 0; hf < 2; hf++) {
            float l = lp[mi][hf];
            l += __shfl_xor_sync(0xffffffffu, l, 1);
            l += __shfl_xor_sync(0xffffffffu, l, 2);
            inv[mi][hf] = 1.f / l;
        }

    uint32_t* obu = reinterpret_cast<uint32_t*>(Ob);
    #pragma unroll
    for (int mi = 0; mi < 2; mi++) {
        int r0 = 32*w + 16*mi + g, r1 = r0 + 8;
        float i0 = inv[mi][0], i1 = inv[mi][1];
        #pragma unroll
        for (int di = 0; di < 8; di++) {
            int cu = h*32 + 4*di + qp;
            if (r0 < HWN)
                obu[((size_t)bt*HWN + r0)*384 + cu] =
                    pack_bf(oacc[mi][di][0]*i0, oacc[mi][di][1]*i0);
            if (r1 < HWN)
                obu[((size_t)bt*HWN + r1)*384 + cu] =
                    pack_bf(oacc[mi][di][2]*i1, oacc[mi][di][3]*i1);
        }
    }
}

// ---------------- launch ----------------------------------------------------
extern "C" void kernel_launch(void* const* d_in, const int* in_sizes, int n_in,
                              void* d_out, int out_size)
{
    const float* x_in  = (const float*)d_in[0];
    const float* Wq_d  = (const float*)d_in[1];
    const float* bq_d  = (const float*)d_in[2];
    const float* Wkv_a = (const float*)d_in[3];
    const float* bkv_a = (const float*)d_in[4];
    const float* Wq_a  = (const float*)d_in[5];
    const float* bq_a  = (const float*)d_in[6];
    const float* Wkv_d = (const float*)d_in[7];
    const float* bkv_d = (const float*)d_in[8];
    const float* Wp_d  = (const float*)d_in[9];
    const float* bp_d  = (const float*)d_in[10];
    const float* Wp_a  = (const float*)d_in[11];
    const float* bp_a  = (const float*)d_in[12];
    float* out = (float*)d_out;

    __nv_bfloat16 *xab, *xdb, *xdnb, *qb, *qab, *kvb, *ob;
    float *xd;
    uint32_t* wp;
    cudaGetSymbolAddress((void**)&xab,  g_xab);
    cudaGetSymbolAddress((void**)&xdb,  g_xdb);
    cudaGetSymbolAddress((void**)&xdnb, g_xdnb);
    cudaGetSymbolAddress((void**)&qb,   g_qb);
    cudaGetSymbolAddress((void**)&qab,  g_qab);
    cudaGetSymbolAddress((void**)&kvb,  g_kvb);
    cudaGetSymbolAddress((void**)&ob,   g_ob);
    cudaGetSymbolAddress((void**)&xd,   g_xd);
    cudaGetSymbolAddress((void**)&wp,   g_wp);

    cudaFuncSetAttribute(attn_tc, cudaFuncAttributeMaxDynamicSharedMemorySize, ATTN_SMEM);
    cudaFuncSetAttribute(gemm_bf, cudaFuncAttributeMaxDynamicSharedMemorySize, GEMM_SMEM);

    // packed-weight offsets (u32 units) — must match packw6_kernel's table
    uint32_t* wp_qd  = wp;
    uint32_t* wp_kva = wp + 294912;
    uint32_t* wp_qa  = wp + 884736;
    uint32_t* wp_kvd = wp + 1179648;
    uint32_t* wp_pd  = wp + 1769472;
    uint32_t* wp_pa  = wp + 2064384;

    // side stream for overlapping the independent stage-a Q GEMM.
    // Fallback: if creation fails, s2 = default stream -> fully serial, still correct.
    cudaStream_t s2 = 0;
    if (cudaStreamCreateWithFlags(&s2, cudaStreamNonBlocking) != cudaSuccess) s2 = 0;
    cudaEvent_t evRoot = nullptr, evQa = nullptr;
    bool ev_ok = (cudaEventCreateWithFlags(&evRoot, cudaEventDisableTiming) == cudaSuccess) &&
                 (cudaEventCreateWithFlags(&evQa,  cudaEventDisableTiming) == cudaSuccess);
    if (!ev_ok) s2 = 0;   // serialize everything on default stream

    packw6_kernel<<<dim3(6, 48, 6), 256>>>(Wq_d, Wkv_a, Wq_a, Wkv_d, Wp_d, Wp_a, wp);
    gather_kernel<<<ROWS, 256>>>(x_in, xab, xdb, xd, out);

    dim3 g768(6, 98), g1536(12, 98);   // M/256 = 98

    // fork: stage-a Q GEMM (depends only on packw + gather) on s2
    if (s2) {
        cudaEventRecord(evRoot, 0);
        cudaStreamWaitEvent(s2, evRoot, 0);
    }
    gemm_bf<<<g768, 256, GEMM_SMEM, s2>>>(xab, wp_qa, bq_a, 0.125f, qab,
                                          nullptr, nullptr, 0.f, ROWS, 768, 768, EPI_BIAS);
    if (s2) cudaEventRecord(evQa, s2);

    // ---- stage d: q from x_d (scaled), kv from x_a ----
    gemm_bf<<<g768,  256, GEMM_SMEM>>>(xdb, wp_qd,  bq_d,  0.125f, qb,  nullptr, nullptr, 0.f, ROWS, 768,  768, EPI_BIAS);
    gemm_bf<<<g1536, 256, GEMM_SMEM>>>(xab, wp_kva, bkv_a, 1.f,    kvb, nullptr, nullptr, 0.f, ROWS, 1536, 768, EPI_BIAS);
    attn_tc<<<BT * NHEAD, AT_THREADS, ATTN_SMEM>>>(qb, kvb, ob);
    gemm_bf<<<g768, 256, GEMM_SMEM>>>(ob, wp_pd, bp_d, 1.f, xdnb, xd, out + ROWS, 1.f, ROWS, 768, 768, EPI_GELU_SUB);

    // join: stage-a needs qab before attn_a (and kvb rewrite needs attn_d done)
    if (s2) cudaStreamWaitEvent(0, evQa, 0);

    // ---- stage a: kv from x_d_new, q = qab (precomputed) ----
    gemm_bf<<<g1536, 256, GEMM_SMEM>>>(xdnb, wp_kvd, bkv_d, 1.f, kvb, nullptr, nullptr, 0.f, ROWS, 1536, 768, EPI_BIAS);
    attn_tc<<<BT * NHEAD, AT_THREADS, ATTN_SMEM>>>(qab, kvb, ob);
    gemm_bf<<<g768, 256, GEMM_SMEM>>>(ob, wp_pa, bp_a, 1.f, nullptr, nullptr, out, -1.f, ROWS, 768, 768, EPI_GELU);
}

// round 15
// speedup vs baseline: 1.5322x; 1.5322x over previous
#include <cuda_runtime.h>
#include <cuda_bf16.h>
#include <math.h>
#include <stdint.h>

// ---------------- problem constants ----------------
#define NB      16
#define BT      128            // NB * 8
#define HWN     196
#define ROWS    25088          // BT * HWN
#define CC      768
#define NHEAD   12
#define HD      64
#define TOKENS  3136

// ---------------- scratch (device globals; no allocs allowed) ----------------
__device__ __align__(16) __nv_bfloat16 g_xab [25088u*768u];
__device__ __align__(16) __nv_bfloat16 g_xdb [25088u*768u];
__device__ __align__(16) __nv_bfloat16 g_xdnb[25088u*768u];
__device__ __align__(16) __nv_bfloat16 g_qb  [25088u*768u];
__device__ __align__(16) __nv_bfloat16 g_kvb [25088u*1536u];
__device__ __align__(16) __nv_bfloat16 g_ob  [25088u*768u];
__device__ float g_xd [25088u*768u];               // fp32 x_d (Xsub)
__device__ __align__(16) uint32_t g_wp[2359296u];  // packed bf16x2 k-pair weights

__device__ __forceinline__ float gelu_f(float x) {
    return 0.5f * x * (1.0f + erff(x * 0.70710678118654752f));
}
__device__ __forceinline__ uint32_t pack_bf(float x, float y) {
    __nv_bfloat162 v = __float22bfloat162_rn(make_float2(x, y));
    return *reinterpret_cast<uint32_t*>(&v);
}
__device__ __forceinline__ void mma_bf16(float* c, const uint32_t* a,
                                         uint32_t b0, uint32_t b1) {
    asm volatile(
        "mma.sync.aligned.m16n8k16.row.col.f32.bf16.bf16.f32 "
        "{%0,%1,%2,%3}, {%4,%5,%6,%7}, {%8,%9}, {%0,%1,%2,%3};\n"
        : "+f"(c[0]), "+f"(c[1]), "+f"(c[2]), "+f"(c[3])
        : "r"(a[0]), "r"(a[1]), "r"(a[2]), "r"(a[3]), "r"(b0), "r"(b1));
}
__device__ __forceinline__ void cp16(uint32_t saddr, const void* g) {
    asm volatile("cp.async.ca.shared.global [%0], [%1], 16;\n"
                 :: "r"(saddr), "l"(g));
}
__device__ __forceinline__ void ldsm_x4(uint32_t& r0, uint32_t& r1,
                                        uint32_t& r2, uint32_t& r3, uint32_t addr) {
    asm volatile("ldmatrix.sync.aligned.m8n8.x4.shared.b16 {%0,%1,%2,%3}, [%4];"
                 : "=r"(r0), "=r"(r1), "=r"(r2), "=r"(r3) : "r"(addr));
}

// ------- weight pack: W[768][N] f32 -> Wp[384][N] u32 (k-pairs) -------------
// z=0,2 (Wq) scaled by 0.125 (exact pow2 -> bit-identical bf16 rounding).
__global__ void packw6_kernel(const float* __restrict__ W0, const float* __restrict__ W1,
                              const float* __restrict__ W2, const float* __restrict__ W3,
                              const float* __restrict__ W4, const float* __restrict__ W5,
                              uint32_t* __restrict__ wp)
{
    const int z = blockIdx.z;
    const float* W; uint32_t off; int N; float sc;
    switch (z) {
        case 0: W = W0; off = 0u;       N = 768;  sc = 0.125f; break;
        case 1: W = W1; off = 294912u;  N = 1536; sc = 1.f;    break;
        case 2: W = W2; off = 884736u;  N = 768;  sc = 0.125f; break;
        case 3: W = W3; off = 1179648u; N = 1536; sc = 1.f;    break;
        case 4: W = W4; off = 1769472u; N = 768;  sc = 1.f;    break;
        default:W = W5; off = 2064384u; N = 768;  sc = 1.f;    break;
    }
    int n  = blockIdx.x * 256 + threadIdx.x;
    int kp = blockIdx.y * 8;
    if (n >= N) return;
    uint32_t* Wp = wp + off;
    #pragma unroll
    for (int i = 0; i < 8; i++) {
        float a = W[(size_t)(2*(kp+i)  ) * N + n] * sc;
        float b = W[(size_t)(2*(kp+i)+1) * N + n] * sc;
        Wp[(size_t)(kp+i) * N + n] = pack_bf(a, b);
    }
}

// ---------------- gather: x_in -> xa_b, xd_b, xd_f32, pool base + zero ------
__global__ void gather_kernel(const float* __restrict__ x_in,
                              __nv_bfloat16* __restrict__ xab,
                              __nv_bfloat16* __restrict__ xdb,
                              float* __restrict__ xd,
                              float* __restrict__ out)
{
    int row = blockIdx.x;              // bt*196 + s
    int bt  = row / HWN, s = row % HWN;
    int b   = bt >> 3,  t2 = bt & 7;
    int tt  = t2 * 2;
    int nt_a = tt >> 2,     t_a = tt & 3;
    int nt_d = (tt+1) >> 2, t_d = (tt+1) & 3;
    size_t base_a = ((size_t)b*TOKENS + (size_t)nt_a*784 + s*4 + t_a) * CC;
    size_t base_d = ((size_t)b*TOKENS + (size_t)nt_d*784 + s*4 + t_d) * CC;

    if (threadIdx.x == 224) out[ROWS + row] = 0.f;   // x_d_out accumulator init

    float suma = 0.f, sumd = 0.f;
    int c4 = threadIdx.x * 4;
    if (c4 < CC) {
        float4 va = *(const float4*)&x_in[base_a + c4];
        float4 vd = *(const float4*)&x_in[base_d + c4];
        uint2 pa; pa.x = pack_bf(va.x, va.y); pa.y = pack_bf(va.z, va.w);
        uint2 pd; pd.x = pack_bf(vd.x, vd.y); pd.y = pack_bf(vd.z, vd.w);
        *(uint2*)&xab[(size_t)row*CC + c4] = pa;
        *(uint2*)&xdb[(size_t)row*CC + c4] = pd;
        *(float4*)&xd[(size_t)row*CC + c4] = vd;
        suma = va.x+va.y+va.z+va.w;
        sumd = vd.x+vd.y+vd.z+vd.w;
    }
    __shared__ float ra[256], rd[256];
    ra[threadIdx.x] = suma; rd[threadIdx.x] = sumd;
    __syncthreads();
    for (int st = 128; st > 0; st >>= 1) {
        if (threadIdx.x < st) {
            ra[threadIdx.x] += ra[threadIdx.x + st];
            rd[threadIdx.x] += rd[threadIdx.x + st];
        }
        __syncthreads();
    }
    if (threadIdx.x == 0)
        out[row] = 0.5f * (rd[0] - ra[0]) * (1.f/768.f);
}

// ---------------- bf16 GEMM (champion config: scalar LDS, CTA 256x128) ------
// At the legacy mma.sync HMMA pipe ceiling — mainloop frozen.
#define APITCH 20
#define BPITCH 136
#define A_STG  (256*APITCH)
#define B_STG  (16*BPITCH)
#define STG_U32 (A_STG + B_STG)
#define GEMM_SMEM (4 * STG_U32 * 4)

#define EPI_BIAS     0
#define EPI_GELU     1
#define EPI_GELU_SUB 2

__global__ __launch_bounds__(256, 1) void gemm_bf(
    const __nv_bfloat16* __restrict__ A, const uint32_t* __restrict__ Wp,
    const float* __restrict__ bias, float bsc,
    __nv_bfloat16* __restrict__ Yb,
    const float* __restrict__ Xsub,
    float* __restrict__ msum, float sgn,
    int M, int N, int K, int epi)
{
    extern __shared__ uint32_t smg[];
    const uint32_t sbase = (uint32_t)__cvta_generic_to_shared(smg);

    const int tid  = threadIdx.x;
    const int bm   = blockIdx.y * 256;
    const int bn   = blockIdx.x * 128;
    const int lane = tid & 31, warp = tid >> 5;
    const int wm   = (warp >> 1) * 64;
    const int wn   = (warp & 1) * 64;
    const int gg   = lane >> 2;
    const int qp   = lane & 3;

    const int nk = K / 32;

    float acc[4][8][4];
    #pragma unroll
    for (int i=0;i<4;i++)
        #pragma unroll
        for (int j=0;j<8;j++)
            #pragma unroll
            for (int r=0;r<4;r++) acc[i][j][r]=0.f;

    auto issue = [&](int kt) {
        const int stg = kt & 3;
        const uint32_t sa = sbase + (stg * STG_U32) * 4;
        #pragma unroll
        for (int i = 0; i < 4; i++) {
            int c = tid + i*256;
            int row = c >> 2, kb = c & 3;
            cp16(sa + (row * APITCH + kb * 4) * 4,
                 &A[(size_t)(bm + row) * K + kt*32 + kb*8]);
        }
        const uint32_t sb = sa + A_STG * 4;
        #pragma unroll
        for (int i = 0; i < 2; i++) {
            int c = tid + i*256;
            int kp = c >> 5, n4 = (c & 31) * 4;
            cp16(sb + (kp * BPITCH + n4) * 4,
                 &Wp[(size_t)(kt*16 + kp) * N + bn + n4]);
        }
        asm volatile("cp.async.commit_group;\n" ::: "memory");
    };

    issue(0); issue(1); issue(2);

    for (int kt = 0; kt < nk; kt++) {
        if (kt < nk - 2)       asm volatile("cp.async.wait_group 2;\n" ::: "memory");
        else if (kt == nk - 2) asm volatile("cp.async.wait_group 1;\n" ::: "memory");
        else                   asm volatile("cp.async.wait_group 0;\n" ::: "memory");
        __syncthreads();
        if (kt + 3 < nk) issue(kt + 3);

        const uint32_t* As_ = smg + (kt & 3) * STG_U32;
        const uint32_t* Bs_ = As_ + A_STG;

        #pragma unroll
        for (int kk = 0; kk < 2; kk++) {
            uint32_t af[4][4], bf[8][2];
            #pragma unroll
            for (int mi = 0; mi < 4; mi++) {
                int rb = wm + mi*16;
                af[mi][0] = As_[(rb+gg  )*APITCH + kk*8 + qp    ];
                af[mi][1] = As_[(rb+gg+8)*APITCH + kk*8 + qp    ];
                af[mi][2] = As_[(rb+gg  )*APITCH + kk*8 + qp + 4];
                af[mi][3] = As_[(rb+gg+8)*APITCH + kk*8 + qp + 4];
            }
            #pragma unroll
            for (int ni = 0; ni < 8; ni++) {
                int cb = wn + ni*8;
                bf[ni][0] = Bs_[(kk*8 + qp    )*BPITCH + cb + gg];
                bf[ni][1] = Bs_[(kk*8 + qp + 4)*BPITCH + cb + gg];
            }
            #pragma unroll
            for (int mi = 0; mi < 4; mi++)
                #pragma unroll
                for (int ni = 0; ni < 8; ni++)
                    mma_bf16(acc[mi][ni], af[mi], bf[ni][0], bf[ni][1]);
        }
    }

    // ---- epilogue ----
    if (epi == EPI_BIAS) {
        #pragma unroll
        for (int mi=0; mi<4; mi++) {
            const int r0 = bm + wm + mi*16 + gg;
            const int r1 = r0 + 8;
            #pragma unroll
            for (int ni=0; ni<8; ni++) {
                const int c = bn + wn + ni*8 + qp*2;
                const float b0v = __ldg(&bias[c])   * bsc;
                const float b1v = __ldg(&bias[c+1]) * bsc;
                *(uint32_t*)&Yb[(size_t)r0*N + c] =
                    pack_bf(acc[mi][ni][0] + b0v, acc[mi][ni][1] + b1v);
                *(uint32_t*)&Yb[(size_t)r1*N + c] =
                    pack_bf(acc[mi][ni][2] + b0v, acc[mi][ni][3] + b1v);
            }
        }
    } else {
        float rs[4][2];
        #pragma unroll
        for (int mi=0;mi<4;mi++) { rs[mi][0]=0.f; rs[mi][1]=0.f; }
        #pragma unroll
        for (int mi=0; mi<4; mi++) {
            const int r0 = bm + wm + mi*16 + gg;
            const int r1 = r0 + 8;
            #pragma unroll
            for (int ni=0; ni<8; ni++) {
                const int c = bn + wn + ni*8 + qp*2;
                const float b0v = __ldg(&bias[c]);
                const float b1v = __ldg(&bias[c+1]);
                float v00 = acc[mi][ni][0] + b0v, v01 = acc[mi][ni][1] + b1v;
                float v10 = acc[mi][ni][2] + b0v, v11 = acc[mi][ni][3] + b1v;
                if (epi == EPI_GELU) {
                    rs[mi][0] += gelu_f(v00) + gelu_f(v01);
                    rs[mi][1] += gelu_f(v10) + gelu_f(v11);
                } else {  // GELU_SUB
                    float2 x0 = *(const float2*)&Xsub[(size_t)r0*N + c];
                    float2 x1 = *(const float2*)&Xsub[(size_t)r1*N + c];
                    float o00 = x0.x - gelu_f(v00), o01 = x0.y - gelu_f(v01);
                    float o10 = x1.x - gelu_f(v10), o11 = x1.y - gelu_f(v11);
                    rs[mi][0] += o00 + o01;
                    rs[mi][1] += o10 + o11;
                    *(uint32_t*)&Yb[(size_t)r0*N + c] = pack_bf(o00, o01);
                    *(uint32_t*)&Yb[(size_t)r1*N + c] = pack_bf(o10, o11);
                }
            }
        }
        #pragma unroll
        for (int mi=0; mi<4; mi++)
            #pragma unroll
            for (int hf=0; hf<2; hf++) {
                float s = rs[mi][hf];
                s += __shfl_xor_sync(0xffffffffu, s, 1);
                s += __shfl_xor_sync(0xffffffffu, s, 2);
                if (qp == 0) {
                    int row = bm + wm + mi*16 + gg + hf*8;
                    atomicAdd(&msum[row], s * sgn * (1.f/768.f));
                }
            }
    }
}

// ---------------- bf16 tensor-core attention, per (bt, head) ----------------
// Q pre-scaled by 1/8 (folded into Wq). 12 unmasked tiles + 1 masked tile.
// ldmatrix.x4 for K and V fragments; S C-frags reused as PV A-frags. occ 2.
#define AT_WARPS   7
#define AT_THREADS 224
#define NKP 208
#define KSP2 36
#define VTP2 116
#define ATTN_SMEM ((NKP*KSP2 + 64*VTP2) * 4)

__global__ __launch_bounds__(AT_THREADS, 2) void attn_tc(
    const __nv_bfloat16* __restrict__ Qb, const __nv_bfloat16* __restrict__ KVb,
    __nv_bfloat16* __restrict__ Ob)
{
    extern __shared__ uint32_t smu[];
    uint32_t* Ks = smu;                    // [208][36]
    uint32_t* Vt = smu + NKP*KSP2;         // [64][116]
    unsigned short* Vs16 = reinterpret_cast<unsigned short*>(Vt);
    const uint32_t KsAddr = (uint32_t)__cvta_generic_to_shared(Ks);
    const uint32_t VtAddr = (uint32_t)__cvta_generic_to_shared(Vt);

    const int bt = blockIdx.x / NHEAD;
    const int h  = blockIdx.x % NHEAD;
    const int tid  = threadIdx.x;
    const int w    = tid >> 5;
    const int lane = tid & 31;
    const int g    = lane >> 2;
    const int qp   = lane & 3;

    // ---- Q fragments first (global LDG; overlaps with smem staging) ----
    uint32_t qa[2][4][4];
    #pragma unroll
    for (int mi = 0; mi < 2; mi++) {
        int r0 = 32*w + 16*mi + g, r1 = r0 + 8;
        const uint32_t* q0 = reinterpret_cast<const uint32_t*>(Qb)
                           + ((size_t)bt*HWN + r0)*384 + h*32;
        const uint32_t* q1 = reinterpret_cast<const uint32_t*>(Qb)
                           + ((size_t)bt*HWN + r1)*384 + h*32;
        bool v0 = (r0 < HWN), v1 = (r1 < HWN);
        #pragma unroll
        for (int kk = 0; kk < 4; kk++) {
            qa[mi][kk][0] = v0 ? q0[8*kk + qp    ] : 0u;
            qa[mi][kk][1] = v1 ? q1[8*kk + qp    ] : 0u;
            qa[mi][kk][2] = v0 ? q0[8*kk + qp + 4] : 0u;
            qa[mi][kk][3] = v1 ? q1[8*kk + qp + 4] : 0u;
        }
    }

    // ---- stage K (u32 copy) and V^T (bf16 scatter) ----
    const uint32_t* kvu = reinterpret_cast<const uint32_t*>(KVb)
                        + (size_t)bt * HWN * 768 + h * 32;
    for (int idx = tid; idx < HWN * 32; idx += AT_THREADS) {
        int r = idx >> 5, j = idx & 31;
        Ks[r*KSP2 + j] = kvu[(size_t)r*768 + j];
        uint32_t v = kvu[(size_t)r*768 + 384 + j];
        int d0 = 2*j;
        Vs16[(d0  )*(VTP2*2) + r] = (unsigned short)(v & 0xffffu);
        Vs16[(d0+1)*(VTP2*2) + r] = (unsigned short)(v >> 16);
    }
    for (int idx = tid; idx < 12*KSP2; idx += AT_THREADS)
        Ks[(196 + idx/KSP2)*KSP2 + idx%KSP2] = 0u;
    for (int idx = tid; idx < 64*6; idx += AT_THREADS)
        Vt[(idx/6)*VTP2 + 98 + idx%6] = 0u;
    __syncthreads();

    const int rowo = (lane & 7) + ((lane >> 4) & 1) * 8;
    const int ko4  = ((lane >> 3) & 1) * 4;
    const uint32_t aK = KsAddr + (rowo * KSP2 + ko4) * 4;
    const uint32_t aV = VtAddr + (rowo * VTP2 + ko4) * 4;

    float oacc[2][8][4];
    #pragma unroll
    for (int mi=0; mi<2; mi++)
        #pragma unroll
        for (int di=0; di<8; di++)
            #pragma unroll
            for (int r=0; r<4; r++) oacc[mi][di][r] = 0.f;
    float lp[2][2] = {{0.f,0.f},{0.f,0.f}};

    for (int nt = 0; nt < 13; nt++) {
        const int j0 = nt * 16;
        float c[2][2][4];
        #pragma unroll
        for (int mi=0;mi<2;mi++)
            #pragma unroll
            for (int hf=0;hf<2;hf++)
                #pragma unroll
                for (int r=0;r<4;r++) c[mi][hf][r]=0.f;

        #pragma unroll
        for (int kk = 0; kk < 4; kk++) {
            uint32_t kb0h0, kb1h0, kb0h1, kb1h1;
            ldsm_x4(kb0h0, kb1h0, kb0h1, kb1h1,
                    aK + (j0 * KSP2 + 8*kk) * 4);
            mma_bf16(c[0][0], qa[0][kk], kb0h0, kb1h0);
            mma_bf16(c[1][0], qa[1][kk], kb0h0, kb1h0);
            mma_bf16(c[0][1], qa[0][kk], kb0h1, kb1h1);
            mma_bf16(c[1][1], qa[1][kk], kb0h1, kb1h1);
        }

        // exp; scale already folded into Q. C-frag becomes PV A-frag.
        uint32_t pa[2][4];
        if (nt < 12) {
            #pragma unroll
            for (int mi = 0; mi < 2; mi++) {
                #pragma unroll
                for (int hf = 0; hf < 2; hf++) {
                    float p00 = __expf(fminf(c[mi][hf][0], 80.f));
                    float p01 = __expf(fminf(c[mi][hf][1], 80.f));
                    float p10 = __expf(fminf(c[mi][hf][2], 80.f));
                    float p11 = __expf(fminf(c[mi][hf][3], 80.f));
                    lp[mi][0] += p00 + p01;
                    lp[mi][1] += p10 + p11;
                    pa[mi][2*hf    ] = pack_bf(p00, p01);
                    pa[mi][2*hf + 1] = pack_bf(p10, p11);
                }
            }
        } else {
            #pragma unroll
            for (int mi = 0; mi < 2; mi++) {
                #pragma unroll
                for (int hf = 0; hf < 2; hf++) {
                    const int col0 = j0 + 8*hf + 2*qp;
                    const bool m0 = (col0     < HWN);
                    const bool m1 = (col0 + 1 < HWN);
                    float p00 = m0 ? __expf(fminf(c[mi][hf][0], 80.f)) : 0.f;
                    float p01 = m1 ? __expf(fminf(c[mi][hf][1], 80.f)) : 0.f;
                    float p10 = m0 ? __expf(fminf(c[mi][hf][2], 80.f)) : 0.f;
                    float p11 = m1 ? __expf(fminf(c[mi][hf][3], 80.f)) : 0.f;
                    lp[mi][0] += p00 + p01;
                    lp[mi][1] += p10 + p11;
                    pa[mi][2*hf    ] = pack_bf(p00, p01);
                    pa[mi][2*hf + 1] = pack_bf(p10, p11);
                }
            }
        }

        const int jp = nt * 8;
        #pragma unroll
        for (int di = 0; di < 8; di += 2) {
            uint32_t vb0a, vb1a, vb0b, vb1b;
            ldsm_x4(vb0a, vb1a, vb0b, vb1b,
                    aV + (8*di * VTP2 + jp) * 4);
            mma_bf16(oacc[0][di  ], pa[0], vb0a, vb1a);
            mma_bf16(oacc[1][di  ], pa[1], vb0a, vb1a);
            mma_bf16(oacc[0][di+1], pa[0], vb0b, vb1b);
            mma_bf16(oacc[1][di+1], pa[1], vb0b, vb1b);
        }
    }

    float inv[2][2];
    #pragma unroll
    for (int mi = 0; mi < 2; mi++)
        #pragma unroll
        for (int hf = 0; hf < 2; hf++) {
            float l = lp[mi][hf];
            l += __shfl_xor_sync(0xffffffffu, l, 1);
            l += __shfl_xor_sync(0xffffffffu, l, 2);
            inv[mi][hf] = 1.f / l;
        }

    uint32_t* obu = reinterpret_cast<uint32_t*>(Ob);
    #pragma unroll
    for (int mi = 0; mi < 2; mi++) {
        int r0 = 32*w + 16*mi + g, r1 = r0 + 8;
        float i0 = inv[mi][0], i1 = inv[mi][1];
        #pragma unroll
        for (int di = 0; di < 8; di++) {
            int cu = h*32 + 4*di + qp;
            if (r0 < HWN)
                obu[((size_t)bt*HWN + r0)*384 + cu] =
                    pack_bf(oacc[mi][di][0]*i0, oacc[mi][di][1]*i0);
            if (r1 < HWN)
                obu[((size_t)bt*HWN + r1)*384 + cu] =
                    pack_bf(oacc[mi][di][2]*i1, oacc[mi][di][3]*i1);
        }
    }
}

// ---------------- launch (single stream, serial) -----------------------------
extern "C" void kernel_launch(void* const* d_in, const int* in_sizes, int n_in,
                              void* d_out, int out_size)
{
    const float* x_in  = (const float*)d_in[0];
    const float* Wq_d  = (const float*)d_in[1];
    const float* bq_d  = (const float*)d_in[2];
    const float* Wkv_a = (const float*)d_in[3];
    const float* bkv_a = (const float*)d_in[4];
    const float* Wq_a  = (const float*)d_in[5];
    const float* bq_a  = (const float*)d_in[6];
    const float* Wkv_d = (const float*)d_in[7];
    const float* bkv_d = (const float*)d_in[8];
    const float* Wp_d  = (const float*)d_in[9];
    const float* bp_d  = (const float*)d_in[10];
    const float* Wp_a  = (const float*)d_in[11];
    const float* bp_a  = (const float*)d_in[12];
    float* out = (float*)d_out;

    __nv_bfloat16 *xab, *xdb, *xdnb, *qb, *kvb, *ob;
    float *xd;
    uint32_t* wp;
    cudaGetSymbolAddress((void**)&xab,  g_xab);
    cudaGetSymbolAddress((void**)&xdb,  g_xdb);
    cudaGetSymbolAddress((void**)&xdnb, g_xdnb);
    cudaGetSymbolAddress((void**)&qb,   g_qb);
    cudaGetSymbolAddress((void**)&kvb,  g_kvb);
    cudaGetSymbolAddress((void**)&ob,   g_ob);
    cudaGetSymbolAddress((void**)&xd,   g_xd);
    cudaGetSymbolAddress((void**)&wp,   g_wp);

    cudaFuncSetAttribute(attn_tc, cudaFuncAttributeMaxDynamicSharedMemorySize, ATTN_SMEM);
    cudaFuncSetAttribute(gemm_bf, cudaFuncAttributeMaxDynamicSharedMemorySize, GEMM_SMEM);

    // packed-weight offsets (u32 units) — must match packw6_kernel's table
    uint32_t* wp_qd  = wp;
    uint32_t* wp_kva = wp + 294912;
    uint32_t* wp_qa  = wp + 884736;
    uint32_t* wp_kvd = wp + 1179648;
    uint32_t* wp_pd  = wp + 1769472;
    uint32_t* wp_pa  = wp + 2064384;

    packw6_kernel<<<dim3(6, 48, 6), 256>>>(Wq_d, Wkv_a, Wq_a, Wkv_d, Wp_d, Wp_a, wp);
    gather_kernel<<<ROWS, 256>>>(x_in, xab, xdb, xd, out);

    dim3 g768(6, 98), g1536(12, 98);   // M/256 = 98

    // ---- stage d: q from x_d (scaled), kv from x_a ----
    gemm_bf<<<g768,  256, GEMM_SMEM>>>(xdb, wp_qd,  bq_d,  0.125f, qb,  nullptr, nullptr, 0.f, ROWS, 768,  768, EPI_BIAS);
    gemm_bf<<<g1536, 256, GEMM_SMEM>>>(xab, wp_kva, bkv_a, 1.f,    kvb, nullptr, nullptr, 0.f, ROWS, 1536, 768, EPI_BIAS);
    attn_tc<<<BT * NHEAD, AT_THREADS, ATTN_SMEM>>>(qb, kvb, ob);
    // x_d_new = x_d - gelu(...): bf16 store + mean into out[ROWS..]
    gemm_bf<<<g768, 256, GEMM_SMEM>>>(ob, wp_pd, bp_d, 1.f, xdnb, xd, out + ROWS, 1.f, ROWS, 768, 768, EPI_GELU_SUB);

    // ---- stage a: q from x_a (scaled), kv from x_d_new ----
    gemm_bf<<<g768,  256, GEMM_SMEM>>>(xab,  wp_qa,  bq_a,  0.125f, qb,  nullptr, nullptr, 0.f, ROWS, 768,  768, EPI_BIAS);
    gemm_bf<<<g1536, 256, GEMM_SMEM>>>(xdnb, wp_kvd, bkv_d, 1.f,    kvb, nullptr, nullptr, 0.f, ROWS, 1536, 768, EPI_BIAS);
    attn_tc<<<BT * NHEAD, AT_THREADS, ATTN_SMEM>>>(qb, kvb, ob);
    // pool_a -= mean(gelu(...)): no stores, atomics only
    gemm_bf<<<g768, 256, GEMM_SMEM>>>(ob, wp_pa, bp_a, 1.f, nullptr, nullptr, out, -1.f, ROWS, 768, 768, EPI_GELU);
}

// round 17
// speedup vs baseline: 1.6029x; 1.0461x over previous
#include <cuda_runtime.h>
#include <cuda_bf16.h>
#include <math.h>
#include <stdint.h>

// ---------------- problem constants ----------------
#define NB      16
#define BT      128            // NB * 8
#define HWN     196
#define ROWS    25088          // BT * HWN
#define CC      768
#define NHEAD   12
#define HD      64
#define TOKENS  3136

// ---------------- scratch (device globals; no allocs allowed) ----------------
__device__ __align__(16) __nv_bfloat16 g_xab [25088u*768u];
__device__ __align__(16) __nv_bfloat16 g_xdb [25088u*768u];
__device__ __align__(16) __nv_bfloat16 g_xdnb[25088u*768u];
__device__ __align__(16) __nv_bfloat16 g_qb  [25088u*768u];
__device__ __align__(16) __nv_bfloat16 g_kvb [25088u*1536u];
__device__ __align__(16) __nv_bfloat16 g_ob  [25088u*768u];
__device__ __align__(16) uint32_t g_wp[2359296u];  // packed bf16x2 k-pair weights

__device__ __forceinline__ float gelu_f(float x) {
    return 0.5f * x * (1.0f + erff(x * 0.70710678118654752f));
}
__device__ __forceinline__ uint32_t pack_bf(float x, float y) {
    __nv_bfloat162 v = __float22bfloat162_rn(make_float2(x, y));
    return *reinterpret_cast<uint32_t*>(&v);
}
__device__ __forceinline__ void mma_bf16(float* c, const uint32_t* a,
                                         uint32_t b0, uint32_t b1) {
    asm volatile(
        "mma.sync.aligned.m16n8k16.row.col.f32.bf16.bf16.f32 "
        "{%0,%1,%2,%3}, {%4,%5,%6,%7}, {%8,%9}, {%0,%1,%2,%3};\n"
        : "+f"(c[0]), "+f"(c[1]), "+f"(c[2]), "+f"(c[3])
        : "r"(a[0]), "r"(a[1]), "r"(a[2]), "r"(a[3]), "r"(b0), "r"(b1));
}
__device__ __forceinline__ void cp16(uint32_t saddr, const void* g) {
    asm volatile("cp.async.ca.shared.global [%0], [%1], 16;\n"
                 :: "r"(saddr), "l"(g));
}
__device__ __forceinline__ void ldsm_x4(uint32_t& r0, uint32_t& r1,
                                        uint32_t& r2, uint32_t& r3, uint32_t addr) {
    asm volatile("ldmatrix.sync.aligned.m8n8.x4.shared.b16 {%0,%1,%2,%3}, [%4];"
                 : "=r"(r0), "=r"(r1), "=r"(r2), "=r"(r3) : "r"(addr));
}

// ------- weight pack: W[768][N] f32 -> Wp[384][N] u32 (k-pairs) -------------
// z=0,2 (Wq) scaled by 0.125 (exact pow2 -> bit-identical bf16 rounding).
__global__ void packw6_kernel(const float* __restrict__ W0, const float* __restrict__ W1,
                              const float* __restrict__ W2, const float* __restrict__ W3,
                              const float* __restrict__ W4, const float* __restrict__ W5,
                              uint32_t* __restrict__ wp)
{
    const int z = blockIdx.z;
    const float* W; uint32_t off; int N; float sc;
    switch (z) {
        case 0: W = W0; off = 0u;       N = 768;  sc = 0.125f; break;
        case 1: W = W1; off = 294912u;  N = 1536; sc = 1.f;    break;
        case 2: W = W2; off = 884736u;  N = 768;  sc = 0.125f; break;
        case 3: W = W3; off = 1179648u; N = 1536; sc = 1.f;    break;
        case 4: W = W4; off = 1769472u; N = 768;  sc = 1.f;    break;
        default:W = W5; off = 2064384u; N = 768;  sc = 1.f;    break;
    }
    int n  = blockIdx.x * 256 + threadIdx.x;
    int kp = blockIdx.y * 8;
    if (n >= N) return;
    uint32_t* Wp = wp + off;
    #pragma unroll
    for (int i = 0; i < 8; i++) {
        float a = W[(size_t)(2*(kp+i)  ) * N + n] * sc;
        float b = W[(size_t)(2*(kp+i)+1) * N + n] * sc;
        Wp[(size_t)(kp+i) * N + n] = pack_bf(a, b);
    }
}

// ---------------- gather: x_in -> xa_b, xd_b (bf16), fp32 means -------------
// out[row]       = 0.5*(mean(x_d) - mean(x_a))   (pool base)
// out[ROWS+row]  = mean(x_d)                     (x_d_out accumulator init)
__global__ void gather_kernel(const float* __restrict__ x_in,
                              __nv_bfloat16* __restrict__ xab,
                              __nv_bfloat16* __restrict__ xdb,
                              float* __restrict__ out)
{
    int row = blockIdx.x;              // bt*196 + s
    int bt  = row / HWN, s = row % HWN;
    int b   = bt >> 3,  t2 = bt & 7;
    int tt  = t2 * 2;
    int nt_a = tt >> 2,     t_a = tt & 3;
    int nt_d = (tt+1) >> 2, t_d = (tt+1) & 3;
    size_t base_a = ((size_t)b*TOKENS + (size_t)nt_a*784 + s*4 + t_a) * CC;
    size_t base_d = ((size_t)b*TOKENS + (size_t)nt_d*784 + s*4 + t_d) * CC;

    float suma = 0.f, sumd = 0.f;
    int c4 = threadIdx.x * 4;
    if (c4 < CC) {
        float4 va = *(const float4*)&x_in[base_a + c4];
        float4 vd = *(const float4*)&x_in[base_d + c4];
        uint2 pa; pa.x = pack_bf(va.x, va.y); pa.y = pack_bf(va.z, va.w);
        uint2 pd; pd.x = pack_bf(vd.x, vd.y); pd.y = pack_bf(vd.z, vd.w);
        *(uint2*)&xab[(size_t)row*CC + c4] = pa;
        *(uint2*)&xdb[(size_t)row*CC + c4] = pd;
        suma = va.x+va.y+va.z+va.w;
        sumd = vd.x+vd.y+vd.z+vd.w;
    }
    __shared__ float ra[256], rd[256];
    ra[threadIdx.x] = suma; rd[threadIdx.x] = sumd;
    __syncthreads();
    for (int st = 128; st > 0; st >>= 1) {
        if (threadIdx.x < st) {
            ra[threadIdx.x] += ra[threadIdx.x + st];
            rd[threadIdx.x] += rd[threadIdx.x + st];
        }
        __syncthreads();
    }
    if (threadIdx.x == 0) {
        out[row]        = 0.5f * (rd[0] - ra[0]) * (1.f/768.f);
        out[ROWS + row] = rd[0] * (1.f/768.f);
    }
}

// ---------------- bf16 GEMM (champion config: scalar LDS, CTA 256x128) ------
// At the legacy mma.sync HMMA pipe ceiling — mainloop frozen.
// Non-BIAS epilogues accumulate gelu row-sums only (msum += sgn*mean(gelu)).
#define APITCH 20
#define BPITCH 136
#define A_STG  (256*APITCH)
#define B_STG  (16*BPITCH)
#define STG_U32 (A_STG + B_STG)
#define GEMM_SMEM (4 * STG_U32 * 4)

#define EPI_BIAS     0
#define EPI_GELU     1
#define EPI_GELU_SUB 2

__global__ __launch_bounds__(256, 1) void gemm_bf(
    const __nv_bfloat16* __restrict__ A, const uint32_t* __restrict__ Wp,
    const float* __restrict__ bias, float bsc,
    __nv_bfloat16* __restrict__ Yb,
    const __nv_bfloat16* __restrict__ Xsub,   // bf16 now
    float* __restrict__ msum, float sgn,
    int M, int N, int K, int epi)
{
    extern __shared__ uint32_t smg[];
    const uint32_t sbase = (uint32_t)__cvta_generic_to_shared(smg);

    const int tid  = threadIdx.x;
    const int bm   = blockIdx.y * 256;
    const int bn   = blockIdx.x * 128;
    const int lane = tid & 31, warp = tid >> 5;
    const int wm   = (warp >> 1) * 64;
    const int wn   = (warp & 1) * 64;
    const int gg   = lane >> 2;
    const int qp   = lane & 3;

    const int nk = K / 32;

    float acc[4][8][4];
    #pragma unroll
    for (int i=0;i<4;i++)
        #pragma unroll
        for (int j=0;j<8;j++)
            #pragma unroll
            for (int r=0;r<4;r++) acc[i][j][r]=0.f;

    auto issue = [&](int kt) {
        const int stg = kt & 3;
        const uint32_t sa = sbase + (stg * STG_U32) * 4;
        #pragma unroll
        for (int i = 0; i < 4; i++) {
            int c = tid + i*256;
            int row = c >> 2, kb = c & 3;
            cp16(sa + (row * APITCH + kb * 4) * 4,
                 &A[(size_t)(bm + row) * K + kt*32 + kb*8]);
        }
        const uint32_t sb = sa + A_STG * 4;
        #pragma unroll
        for (int i = 0; i < 2; i++) {
            int c = tid + i*256;
            int kp = c >> 5, n4 = (c & 31) * 4;
            cp16(sb + (kp * BPITCH + n4) * 4,
                 &Wp[(size_t)(kt*16 + kp) * N + bn + n4]);
        }
        asm volatile("cp.async.commit_group;\n" ::: "memory");
    };

    issue(0); issue(1); issue(2);

    for (int kt = 0; kt < nk; kt++) {
        if (kt < nk - 2)       asm volatile("cp.async.wait_group 2;\n" ::: "memory");
        else if (kt == nk - 2) asm volatile("cp.async.wait_group 1;\n" ::: "memory");
        else                   asm volatile("cp.async.wait_group 0;\n" ::: "memory");
        __syncthreads();
        if (kt + 3 < nk) issue(kt + 3);

        const uint32_t* As_ = smg + (kt & 3) * STG_U32;
        const uint32_t* Bs_ = As_ + A_STG;

        #pragma unroll
        for (int kk = 0; kk < 2; kk++) {
            uint32_t af[4][4], bf[8][2];
            #pragma unroll
            for (int mi = 0; mi < 4; mi++) {
                int rb = wm + mi*16;
                af[mi][0] = As_[(rb+gg  )*APITCH + kk*8 + qp    ];
                af[mi][1] = As_[(rb+gg+8)*APITCH + kk*8 + qp    ];
                af[mi][2] = As_[(rb+gg  )*APITCH + kk*8 + qp + 4];
                af[mi][3] = As_[(rb+gg+8)*APITCH + kk*8 + qp + 4];
            }
            #pragma unroll
            for (int ni = 0; ni < 8; ni++) {
                int cb = wn + ni*8;
                bf[ni][0] = Bs_[(kk*8 + qp    )*BPITCH + cb + gg];
                bf[ni][1] = Bs_[(kk*8 + qp + 4)*BPITCH + cb + gg];
            }
            #pragma unroll
            for (int mi = 0; mi < 4; mi++)
                #pragma unroll
                for (int ni = 0; ni < 8; ni++)
                    mma_bf16(acc[mi][ni], af[mi], bf[ni][0], bf[ni][1]);
        }
    }

    // ---- epilogue ----
    if (epi == EPI_BIAS) {
        #pragma unroll
        for (int mi=0; mi<4; mi++) {
            const int r0 = bm + wm + mi*16 + gg;
            const int r1 = r0 + 8;
            #pragma unroll
            for (int ni=0; ni<8; ni++) {
                const int c = bn + wn + ni*8 + qp*2;
                const float b0v = __ldg(&bias[c])   * bsc;
                const float b1v = __ldg(&bias[c+1]) * bsc;
                *(uint32_t*)&Yb[(size_t)r0*N + c] =
                    pack_bf(acc[mi][ni][0] + b0v, acc[mi][ni][1] + b1v);
                *(uint32_t*)&Yb[(size_t)r1*N + c] =
                    pack_bf(acc[mi][ni][2] + b0v, acc[mi][ni][3] + b1v);
            }
        }
    } else {
        float rs[4][2];                      // gelu row sums [mi][r0/r1]
        #pragma unroll
        for (int mi=0;mi<4;mi++) { rs[mi][0]=0.f; rs[mi][1]=0.f; }
        #pragma unroll
        for (int mi=0; mi<4; mi++) {
            const int r0 = bm + wm + mi*16 + gg;
            const int r1 = r0 + 8;
            #pragma unroll
            for (int ni=0; ni<8; ni++) {
                const int c = bn + wn + ni*8 + qp*2;
                const float b0v = __ldg(&bias[c]);
                const float b1v = __ldg(&bias[c+1]);
                float g00 = gelu_f(acc[mi][ni][0] + b0v);
                float g01 = gelu_f(acc[mi][ni][1] + b1v);
                float g10 = gelu_f(acc[mi][ni][2] + b0v);
                float g11 = gelu_f(acc[mi][ni][3] + b1v);
                rs[mi][0] += g00 + g01;
                rs[mi][1] += g10 + g11;
                if (epi == EPI_GELU_SUB) {
                    float2 x0 = __bfloat1622float2(
                        *(const __nv_bfloat162*)&Xsub[(size_t)r0*N + c]);
                    float2 x1 = __bfloat1622float2(
                        *(const __nv_bfloat162*)&Xsub[(size_t)r1*N + c]);
                    *(uint32_t*)&Yb[(size_t)r0*N + c] = pack_bf(x0.x - g00, x0.y - g01);
                    *(uint32_t*)&Yb[(size_t)r1*N + c] = pack_bf(x1.x - g10, x1.y - g11);
                }
            }
        }
        // quad-reduce over qp, one atomic per row per warp
        #pragma unroll
        for (int mi=0; mi<4; mi++)
            #pragma unroll
            for (int hf=0; hf<2; hf++) {
                float s = rs[mi][hf];
                s += __shfl_xor_sync(0xffffffffu, s, 1);
                s += __shfl_xor_sync(0xffffffffu, s, 2);
                if (qp == 0) {
                    int row = bm + wm + mi*16 + gg + hf*8;
                    atomicAdd(&msum[row], s * sgn * (1.f/768.f));
                }
            }
    }
}

// ---------------- bf16 tensor-core attention, per (bt, head) ----------------
// Q pre-scaled by 1/8 (folded into Wq). 12 unmasked tiles + 1 masked tile.
// ldmatrix.x4 for K and V fragments; S C-frags reused as PV A-frags. occ 2.
#define AT_WARPS   7
#define AT_THREADS 224
#define NKP 208
#define KSP2 36
#define VTP2 116
#define ATTN_SMEM ((NKP*KSP2 + 64*VTP2) * 4)

__global__ __launch_bounds__(AT_THREADS, 2) void attn_tc(
    const __nv_bfloat16* __restrict__ Qb, const __nv_bfloat16* __restrict__ KVb,
    __nv_bfloat16* __restrict__ Ob)
{
    extern __shared__ uint32_t smu[];
    uint32_t* Ks = smu;                    // [208][36]
    uint32_t* Vt = smu + NKP*KSP2;         // [64][116]
    unsigned short* Vs16 = reinterpret_cast<unsigned short*>(Vt);
    const uint32_t KsAddr = (uint32_t)__cvta_generic_to_shared(Ks);
    const uint32_t VtAddr = (uint32_t)__cvta_generic_to_shared(Vt);

    const int bt = blockIdx.x / NHEAD;
    const int h  = blockIdx.x % NHEAD;
    const int tid  = threadIdx.x;
    const int w    = tid >> 5;
    const int lane = tid & 31;
    const int g    = lane >> 2;
    const int qp   = lane & 3;

    // ---- Q fragments first (global LDG; overlaps with smem staging) ----
    uint32_t qa[2][4][4];
    #pragma unroll
    for (int mi = 0; mi < 2; mi++) {
        int r0 = 32*w + 16*mi + g, r1 = r0 + 8;
        const uint32_t* q0 = reinterpret_cast<const uint32_t*>(Qb)
                           + ((size_t)bt*HWN + r0)*384 + h*32;
        const uint32_t* q1 = reinterpret_cast<const uint32_t*>(Qb)
                           + ((size_t)bt*HWN + r1)*384 + h*32;
        bool v0 = (r0 < HWN), v1 = (r1 < HWN);
        #pragma unroll
        for (int kk = 0; kk < 4; kk++) {
            qa[mi][kk][0] = v0 ? q0[8*kk + qp    ] : 0u;
            qa[mi][kk][1] = v1 ? q1[8*kk + qp    ] : 0u;
            qa[mi][kk][2] = v0 ? q0[8*kk + qp + 4] : 0u;
            qa[mi][kk][3] = v1 ? q1[8*kk + qp + 4] : 0u;
        }
    }

    // ---- stage K (u32 copy) and V^T (bf16 scatter) ----
    const uint32_t* kvu = reinterpret_cast<const uint32_t*>(KVb)
                        + (size_t)bt * HWN * 768 + h * 32;
    for (int idx = tid; idx < HWN * 32; idx += AT_THREADS) {
        int r = idx >> 5, j = idx & 31;
        Ks[r*KSP2 + j] = kvu[(size_t)r*768 + j];
        uint32_t v = kvu[(size_t)r*768 + 384 + j];
        int d0 = 2*j;
        Vs16[(d0  )*(VTP2*2) + r] = (unsigned short)(v & 0xffffu);
        Vs16[(d0+1)*(VTP2*2) + r] = (unsigned short)(v >> 16);
    }
    for (int idx = tid; idx < 12*KSP2; idx += AT_THREADS)
        Ks[(196 + idx/KSP2)*KSP2 + idx%KSP2] = 0u;
    for (int idx = tid; idx < 64*6; idx += AT_THREADS)
        Vt[(idx/6)*VTP2 + 98 + idx%6] = 0u;
    __syncthreads();

    const int rowo = (lane & 7) + ((lane >> 4) & 1) * 8;
    const int ko4  = ((lane >> 3) & 1) * 4;
    const uint32_t aK = KsAddr + (rowo * KSP2 + ko4) * 4;
    const uint32_t aV = VtAddr + (rowo * VTP2 + ko4) * 4;

    float oacc[2][8][4];
    #pragma unroll
    for (int mi=0; mi<2; mi++)
        #pragma unroll
        for (int di=0; di<8; di++)
            #pragma unroll
            for (int r=0; r<4; r++) oacc[mi][di][r] = 0.f;
    float lp[2][2] = {{0.f,0.f},{0.f,0.f}};

    for (int nt = 0; nt < 13; nt++) {
        const int j0 = nt * 16;
        float c[2][2][4];
        #pragma unroll
        for (int mi=0;mi<2;mi++)
            #pragma unroll
            for (int hf=0;hf<2;hf++)
                #pragma unroll
                for (int r=0;r<4;r++) c[mi][hf][r]=0.f;

        #pragma unroll
        for (int kk = 0; kk < 4; kk++) {
            uint32_t kb0h0, kb1h0, kb0h1, kb1h1;
            ldsm_x4(kb0h0, kb1h0, kb0h1, kb1h1,
                    aK + (j0 * KSP2 + 8*kk) * 4);
            mma_bf16(c[0][0], qa[0][kk], kb0h0, kb1h0);
            mma_bf16(c[1][0], qa[1][kk], kb0h0, kb1h0);
            mma_bf16(c[0][1], qa[0][kk], kb0h1, kb1h1);
            mma_bf16(c[1][1], qa[1][kk], kb0h1, kb1h1);
        }

        // exp (scale folded into Q; |s| small -> no clamp). C-frag -> PV A-frag.
        uint32_t pa[2][4];
        if (nt < 12) {
            #pragma unroll
            for (int mi = 0; mi < 2; mi++) {
                #pragma unroll
                for (int hf = 0; hf < 2; hf++) {
                    float p00 = __expf(c[mi][hf][0]);
                    float p01 = __expf(c[mi][hf][1]);
                    float p10 = __expf(c[mi][hf][2]);
                    float p11 = __expf(c[mi][hf][3]);
                    lp[mi][0] += p00 + p01;
                    lp[mi][1] += p10 + p11;
                    pa[mi][2*hf    ] = pack_bf(p00, p01);
                    pa[mi][2*hf + 1] = pack_bf(p10, p11);
                }
            }
        } else {
            #pragma unroll
            for (int mi = 0; mi < 2; mi++) {
                #pragma unroll
                for (int hf = 0; hf < 2; hf++) {
                    const int col0 = j0 + 8*hf + 2*qp;
                    const bool m0 = (col0     < HWN);
                    const bool m1 = (col0 + 1 < HWN);
                    float p00 = m0 ? __expf(c[mi][hf][0]) : 0.f;
                    float p01 = m1 ? __expf(c[mi][hf][1]) : 0.f;
                    float p10 = m0 ? __expf(c[mi][hf][2]) : 0.f;
                    float p11 = m1 ? __expf(c[mi][hf][3]) : 0.f;
                    lp[mi][0] += p00 + p01;
                    lp[mi][1] += p10 + p11;
                    pa[mi][2*hf    ] = pack_bf(p00, p01);
                    pa[mi][2*hf + 1] = pack_bf(p10, p11);
                }
            }
        }

        const int jp = nt * 8;
        #pragma unroll
        for (int di = 0; di < 8; di += 2) {
            uint32_t vb0a, vb1a, vb0b, vb1b;
            ldsm_x4(vb0a, vb1a, vb0b, vb1b,
                    aV + (8*di * VTP2 + jp) * 4);
            mma_bf16(oacc[0][di  ], pa[0], vb0a, vb1a);
            mma_bf16(oacc[1][di  ], pa[1], vb0a, vb1a);
            mma_bf16(oacc[0][di+1], pa[0], vb0b, vb1b);
            mma_bf16(oacc[1][di+1], pa[1], vb0b, vb1b);
        }
    }

    float inv[2][2];
    #pragma unroll
    for (int mi = 0; mi < 2; mi++)
        #pragma unroll
        for (int hf = 0; hf < 2; hf++) {
            float l = lp[mi][hf];
            l += __shfl_xor_sync(0xffffffffu, l, 1);
            l += __shfl_xor_sync(0xffffffffu, l, 2);
            inv[mi][hf] = 1.f / l;
        }

    uint32_t* obu = reinterpret_cast<uint32_t*>(Ob);
    #pragma unroll
    for (int mi = 0; mi < 2; mi++) {
        int r0 = 32*w + 16*mi + g, r1 = r0 + 8;
        float i0 = inv[mi][0], i1 = inv[mi][1];
        #pragma unroll
        for (int di = 0; di < 8; di++) {
            int cu = h*32 + 4*di + qp;
            if (r0 < HWN)
                obu[((size_t)bt*HWN + r0)*384 + cu] =
                    pack_bf(oacc[mi][di][0]*i0, oacc[mi][di][1]*i0);
            if (r1 < HWN)
                obu[((size_t)bt*HWN + r1)*384 + cu] =
                    pack_bf(oacc[mi][di][2]*i1, oacc[mi][di][3]*i1);
        }
    }
}

// ---------------- launch (single stream, serial) -----------------------------
extern "C" void kernel_launch(void* const* d_in, const int* in_sizes, int n_in,
                              void* d_out, int out_size)
{
    const float* x_in  = (const float*)d_in[0];
    const float* Wq_d  = (const float*)d_in[1];
    const float* bq_d  = (const float*)d_in[2];
    const float* Wkv_a = (const float*)d_in[3];
    const float* bkv_a = (const float*)d_in[4];
    const float* Wq_a  = (const float*)d_in[5];
    const float* bq_a  = (const float*)d_in[6];
    const float* Wkv_d = (const float*)d_in[7];
    const float* bkv_d = (const float*)d_in[8];
    const float* Wp_d  = (const float*)d_in[9];
    const float* bp_d  = (const float*)d_in[10];
    const float* Wp_a  = (const float*)d_in[11];
    const float* bp_a  = (const float*)d_in[12];
    float* out = (float*)d_out;

    __nv_bfloat16 *xab, *xdb, *xdnb, *qb, *kvb, *ob;
    uint32_t* wp;
    cudaGetSymbolAddress((void**)&xab,  g_xab);
    cudaGetSymbolAddress((void**)&xdb,  g_xdb);
    cudaGetSymbolAddress((void**)&xdnb, g_xdnb);
    cudaGetSymbolAddress((void**)&qb,   g_qb);
    cudaGetSymbolAddress((void**)&kvb,  g_kvb);
    cudaGetSymbolAddress((void**)&ob,   g_ob);
    cudaGetSymbolAddress((void**)&wp,   g_wp);

    cudaFuncSetAttribute(attn_tc, cudaFuncAttributeMaxDynamicSharedMemorySize, ATTN_SMEM);
    cudaFuncSetAttribute(gemm_bf, cudaFuncAttributeMaxDynamicSharedMemorySize, GEMM_SMEM);

    // packed-weight offsets (u32 units) — must match packw6_kernel's table
    uint32_t* wp_qd  = wp;
    uint32_t* wp_kva = wp + 294912;
    uint32_t* wp_qa  = wp + 884736;
    uint32_t* wp_kvd = wp + 1179648;
    uint32_t* wp_pd  = wp + 1769472;
    uint32_t* wp_pa  = wp + 2064384;

    packw6_kernel<<<dim3(6, 48, 6), 256>>>(Wq_d, Wkv_a, Wq_a, Wkv_d, Wp_d, Wp_a, wp);
    gather_kernel<<<ROWS, 256>>>(x_in, xab, xdb, out);

    dim3 g768(6, 98), g1536(12, 98);   // M/256 = 98

    // ---- stage d: q from x_d (scaled), kv from x_a ----
    gemm_bf<<<g768,  256, GEMM_SMEM>>>(xdb, wp_qd,  bq_d,  0.125f, qb,  nullptr, nullptr, 0.f, ROWS, 768,  768, EPI_BIAS);
    gemm_bf<<<g1536, 256, GEMM_SMEM>>>(xab, wp_kva, bkv_a, 1.f,    kvb, nullptr, nullptr, 0.f, ROWS, 1536, 768, EPI_BIAS);
    attn_tc<<<BT * NHEAD, AT_THREADS, ATTN_SMEM>>>(qb, kvb, ob);
    // x_d_new = bf16(x_d) - gelu(...): bf16 store; out[ROWS..] -= mean(gelu)
    gemm_bf<<<g768, 256, GEMM_SMEM>>>(ob, wp_pd, bp_d, 1.f, xdnb, xdb, out + ROWS, -1.f, ROWS, 768, 768, EPI_GELU_SUB);

    // ---- stage a: q from x_a (scaled), kv from x_d_new ----
    gemm_bf<<<g768,  256, GEMM_SMEM>>>(xab,  wp_qa,  bq_a,  0.125f, qb,  nullptr, nullptr, 0.f, ROWS, 768,  768, EPI_BIAS);
    gemm_bf<<<g1536, 256, GEMM_SMEM>>>(xdnb, wp_kvd, bkv_d, 1.f,    kvb, nullptr, nullptr, 0.f, ROWS, 1536, 768, EPI_BIAS);
    attn_tc<<<BT * NHEAD, AT_THREADS, ATTN_SMEM>>>(qb, kvb, ob);
    // pool_a -= mean(gelu(...)): no stores, atomics only
    gemm_bf<<<g768, 256, GEMM_SMEM>>>(ob, wp_pa, bp_a, 1.f, nullptr, nullptr, out, -1.f, ROWS, 768, 768, EPI_GELU);
}